// round 14
// baseline (speedup 1.0000x reference)
#include <cuda_runtime.h>
#include <cstdint>

// YOLO loss "slim4": R10 structure (grid-stride, no smem staging, no barriers)
// with the softmax x[20] register array eliminated — class logits are re-read
// from L1 on each pass (obj cells only, rows L1-resident). This cuts live regs
// ~20, allowing 4 CTAs/SM at 256 threads without spills.

#define THREADS   256
#define NPART_MAX 2048

__device__ float        g_part[6][NPART_MAX];
__device__ unsigned int g_count = 0;

__device__ __forceinline__ void block_reduce6(float* vals, float* s_red, int tid)
{
    #pragma unroll
    for (int v = 0; v < 6; v++) {
        #pragma unroll
        for (int off = 16; off > 0; off >>= 1)
            vals[v] += __shfl_down_sync(0xffffffffu, vals[v], off);
    }
    const int warp = tid >> 5;
    const int lane = tid & 31;
    if (lane == 0) {
        #pragma unroll
        for (int v = 0; v < 6; v++) s_red[warp * 6 + v] = vals[v];
    }
    __syncthreads();
    if (tid == 0) {
        #pragma unroll
        for (int v = 0; v < 6; v++) {
            float s = 0.f;
            #pragma unroll
            for (int w2 = 0; w2 < THREADS / 32; w2++) s += s_red[w2 * 6 + v];
            vals[v] = s;
        }
    }
}

__global__ __launch_bounds__(THREADS, 4)
void yolo_slim4(const float* __restrict__ pred,
                const float* __restrict__ target,
                const int*   __restrict__ choice,
                float*       __restrict__ out,
                int n_cells)
{
    __shared__ float s_red[(THREADS / 32) * 6];
    __shared__ bool  s_last;

    const int tid = threadIdx.x;
    float acc[6] = {0.f, 0.f, 0.f, 0.f, 0.f, 0.f};

    const long long stride = (long long)gridDim.x * THREADS;

    for (long long cell = (long long)blockIdx.x * THREADS + tid;
         cell < n_cells; cell += stride)
    {
        const float* p = pred   + cell * 30;
        const float* t = target + cell * 30;

        // always-needed scalars (independent loads, front-batched)
        const float t4 = t[4];
        const int   cv = choice[cell];
        const float p4 = p[4];
        const float p9 = p[9];
        const float t9 = t[9];

        if (t4 > 0.f) {
            // ---- obj cell (~10%) ----
            const bool c = cv != 0;
            const int  o = c ? 0 : 5;
            acc[4] += 1.f;

            float dx = p[o + 0] - t[o + 0];
            float dy = p[o + 1] - t[o + 1];
            float dw = p[o + 2] - sqrtf(t[o + 2]);
            float dh = p[o + 3] - sqrtf(t[o + 3]);
            acc[0] += 0.5f * (dx * dx + dy * dy) + 0.5f * (dw * dw + dh * dh);

            float d = (c ? p4 : p9) - (c ? t4 : t9);
            acc[2] += d * d;

            // class CE with multi-pass L1 re-reads (no x[20] register array).
            // pc2 is 8B-aligned (offset 40B in a 120B row).
            const float2* pc2 = (const float2*)(p + 10);
            const float2* tc2 = (const float2*)(t + 10);

            // pass A: max logit
            float mx = -1e30f;
            #pragma unroll
            for (int k = 0; k < 10; k++) {
                float2 v = pc2[k];
                mx = fmaxf(mx, fmaxf(v.x, v.y));
            }
            // pass B: softmax denominator
            float den = 0.f;
            #pragma unroll
            for (int k = 0; k < 10; k++) {
                float2 v = pc2[k];
                den += __expf(v.x - mx) + __expf(v.y - mx);
            }
            float inv = __fdividef(1.f, den);
            // pass C: den2 = sum exp(sm_k); sm in [0,1] -> shiftless LSE safe
            float den2 = 0.f;
            #pragma unroll
            for (int k = 0; k < 10; k++) {
                float2 v = pc2[k];
                den2 += __expf(__expf(v.x - mx) * inv)
                      + __expf(__expf(v.y - mx) * inv);
            }
            float lse2 = __logf(den2);
            // pass D: argmax of target classes (first max), carry pred logit
            float bm = -1e30f, xsel = 0.f;
            #pragma unroll
            for (int k = 0; k < 10; k++) {
                float2 tv = tc2[k];
                float2 pv = pc2[k];
                if (tv.x > bm) { bm = tv.x; xsel = pv.x; }
                if (tv.y > bm) { bm = tv.y; xsel = pv.y; }
            }
            acc[1] += lse2 - __expf(xsel - mx) * inv;
        } else {
            // ---- noobj cell: only already-loaded scalars ----
            acc[5] += 1.f;
            float d0 = p4 - t4;            // t4 == 0 here
            float d1 = p9 - t9;
            acc[3] += d0 * d0 + d1 * d1;
        }
    }

    __syncthreads();
    block_reduce6(acc, s_red, tid);

    if (tid == 0) {
        #pragma unroll
        for (int v = 0; v < 6; v++) g_part[v][blockIdx.x] = acc[v];
        __threadfence();
        unsigned int ticket = atomicAdd(&g_count, 1u);
        s_last = (ticket == gridDim.x - 1);
    }
    __syncthreads();

    if (s_last) {
        __threadfence();
        const int npart = gridDim.x;
        float a[6] = {0.f, 0.f, 0.f, 0.f, 0.f, 0.f};
        for (int i = tid; i < npart; i += THREADS) {
            #pragma unroll
            for (int v = 0; v < 6; v++) a[v] += g_part[v][i];
        }
        __syncthreads();
        block_reduce6(a, s_red, tid);
        if (tid == 0) {
            float n_obj = fmaxf(a[4], 1.f);
            float n_no  = fmaxf(a[5], 1.f);
            out[0] = 5.0f * a[0];          // loc_loss
            out[1] = a[1] / n_obj;         // cls_loss
            out[2] = a[2];                 // obj_loss
            out[3] = 0.5f * a[3] / n_no;   // noobj_loss
            g_count = 0;                   // reset for next graph replay
        }
    }
}

extern "C" void kernel_launch(void* const* d_in, const int* in_sizes, int n_in,
                              void* d_out, int out_size)
{
    const float* pred   = (const float*)d_in[0];
    const float* target = (const float*)d_in[1];
    const int*   choice = (const int*)d_in[2];
    float* out = (float*)d_out;

    const int n_cells = in_sizes[2];

    int grid = 4 * 148;                      // 4 CTAs/SM x 256 thr = 32 warps/SM
    long long want = ((long long)n_cells + THREADS - 1) / THREADS;
    if ((long long)grid > want) grid = (int)want;
    if (grid < 1) grid = 1;
    if (grid > NPART_MAX) grid = NPART_MAX;

    yolo_slim4<<<grid, THREADS>>>(pred, target, choice, out, n_cells);
}